// round 2
// baseline (speedup 1.0000x reference)
#include <cuda_runtime.h>

// BrockHommes: B=8192 independent rows, T=4096 strictly-sequential steps.
// One thread per row; pure dependency-latency bound. All x2/x3-dependent work
// (c_k, nbl2, cmax/cmin) is hoisted so the x1->x_t chain is:
//   sL -> M=max(sL*cmax, sL*cmin) -> arg_k=fma(sL,c_k,-M) -> ex2 -> den -> rcp -> fma
// ~90 cycles/step. True max => den in [1,4] => raw rcp.approx is safe (no NR).

#define B_CONST 8192
#define T_CONST 4096

__device__ __forceinline__ float ex2a(float x) {
    float y;
    asm("ex2.approx.f32 %0, %1;" : "=f"(y) : "f"(x));
    return y;
}
__device__ __forceinline__ float rcpa(float x) {
    float y;
    asm("rcp.approx.f32 %0, %1;" : "=f"(y) : "f"(x));
    return y;
}

__global__ void __launch_bounds__(64, 1)
bh_kernel(const float* __restrict__ theta,
          const float* __restrict__ eps,
          float* __restrict__ out)
{
    int b = blockIdx.x * 64 + threadIdx.x;
    if (b >= B_CONST) return;

    const float* th = theta + b * 11;
    const float beta = th[0];
    const float g0 = th[1], g1 = th[2], g2 = th[3], g3 = th[4];
    const float b0 = th[5], b1 = th[6], b2 = th[7], b3 = th[8];
    const float sigma = th[9];
    const float r = th[10];

    const float R    = 1.0f + r;
    const float invR = 1.0f / R;                         // one accurate div
    const float bl   = beta * 1.44269504088896340736f;   // beta * log2(e)
    const float blR  = bl * R;
    const float sigR = sigma * invR;
    // numerator constants with 1/R folded in:
    const float gi0 = g0 * invR, gi1 = g1 * invR, gi2 = g2 * invR, gi3 = g3 * invR;
    const float bi0 = b0 * invR, bi1 = b1 * invR, bi2 = b2 * invR, bi3 = b3 * invR;

    const float4* ep4 = reinterpret_cast<const float4*>(eps + (size_t)b * T_CONST);
    float4*       o4  = reinterpret_cast<float4*>(out + (size_t)b * T_CONST);
    const int T4 = T_CONST / 4;

    float x1 = 0.0f, x2 = 0.0f, x3 = 0.0f;

    // ---- prep for the first step (depends on x2, x3 = 0) ----
    float Rx2  = R * x2;
    float nbl2 = blR * x2;                  // bl * R * x2
    float c0 = fmaf(g0, x3, b0 - Rx2);
    float c1 = fmaf(g1, x3, b1 - Rx2);
    float c2 = fmaf(g2, x3, b2 - Rx2);
    float c3 = fmaf(g3, x3, b3 - Rx2);
    float cmax = fmaxf(fmaxf(c0, c1), fmaxf(c2, c3));
    float cmin = fminf(fminf(c0, c1), fminf(c2, c3));

    // distance-2 prefetch pipeline for eps
    float4 buf0 = ep4[0];
    float4 buf1 = ep4[1];

    for (int i = 0; i < T4; ++i) {
        float4 ev = buf0;
        buf0 = buf1;
        if (i + 2 < T4) buf1 = ep4[i + 2];

        // precompute eps*sigma/R off the path
        float e0s = ev.x * sigR, e1s = ev.y * sigR, e2s = ev.z * sigR, e3s = ev.w * sigR;
        float eo[4] = {e0s, e1s, e2s, e3s};
        float xo[4];

        #pragma unroll
        for (int k = 0; k < 4; ++k) {
            // ---- critical path: everything below the prep depends on x1 ----
            float sL = fmaf(bl, x1, -nbl2);          // bl*(x1 - R*x2)

            // exact max of t_k = sL*c_k in two ops (sign-agnostic)
            float Ma = sL * cmax;
            float Mb = sL * cmin;
            float M  = fmaxf(Ma, Mb);

            float a0 = fmaf(sL, c0, -M);             // t_k - M, all <= 0
            float a1 = fmaf(sL, c1, -M);
            float a2 = fmaf(sL, c2, -M);
            float a3 = fmaf(sL, c3, -M);

            float p0 = ex2a(a0);
            float p1 = ex2a(a1);
            float p2 = ex2a(a2);
            float p3 = ex2a(a3);

            // numerator with invR folded into the regime means
            float m0 = fmaf(gi0, x1, bi0);
            float m1 = fmaf(gi1, x1, bi1);
            float m2 = fmaf(gi2, x1, bi2);
            float m3 = fmaf(gi3, x1, bi3);

            float d01 = p0 + p1;
            float d23 = p2 + p3;
            float den = d01 + d23;                   // in [1,4]

            float n01 = fmaf(p1, m1, p0 * m0);
            float n23 = fmaf(p3, m3, p2 * m2);
            float num = n01 + n23;

            float rd = rcpa(den);                    // den in [1,4] -> approx safe
            float xt = fmaf(num, rd, eo[k]);         // (sum w*m)/R + eps*sigma/R

            // ---- shift state, then prep for the NEXT step (off next path) ----
            x3 = x2; x2 = x1; x1 = xt;
            xo[k] = xt;

            Rx2  = R * x2;
            nbl2 = blR * x2;
            c0 = fmaf(g0, x3, b0 - Rx2);
            c1 = fmaf(g1, x3, b1 - Rx2);
            c2 = fmaf(g2, x3, b2 - Rx2);
            c3 = fmaf(g3, x3, b3 - Rx2);
            cmax = fmaxf(fmaxf(c0, c1), fmaxf(c2, c3));
            cmin = fminf(fminf(c0, c1), fminf(c2, c3));
        }

        o4[i] = make_float4(xo[0], xo[1], xo[2], xo[3]);
    }
}

extern "C" void kernel_launch(void* const* d_in, const int* in_sizes, int n_in,
                              void* d_out, int out_size)
{
    const float* theta = (const float*)d_in[0];   // (B, 11) float32
    const float* eps   = (const float*)d_in[1];   // (B, T)  float32
    float*       out   = (float*)d_out;           // (B, T)  float32

    bh_kernel<<<B_CONST / 64, 64>>>(theta, eps, out);
}